// round 12
// baseline (speedup 1.0000x reference)
#include <cuda_runtime.h>
#include <cstdint>
#include <cstddef>

#define T_STEPS 1024
#define BATCH   64
#define FDIM    256
#define HDIM    512
#define G3      (3*HDIM)   /* 1536 */

typedef unsigned long long ull;

// ---------------- static scratch (allocation-free per harness rules) ----------------
__device__ float    g_xg[(size_t)T_STEPS * BATCH * G3];   // input projections
__device__ float    g_h[2][BATCH * HDIM];                 // ping-pong hidden state [b][pos(k)]
__device__ unsigned g_bar[8 * 32];                        // per-batch-group barrier (padded lines)

// ---------------- helpers ----------------
__device__ __forceinline__ ull ffma2(ull a, ull b, ull c) {
    ull d;
    asm("fma.rn.f32x2 %0, %1, %2, %3;" : "=l"(d) : "l"(a), "l"(b), "l"(c));
    return d;
}
__device__ __forceinline__ ull dup2(float a) {
    ull d;
    asm("mov.b64 %0, {%1, %1};" : "=l"(d) : "f"(a));
    return d;
}
__device__ __forceinline__ float lo32(ull v) { return __int_as_float((int)(unsigned)(v & 0xffffffffull)); }
__device__ __forceinline__ float hi32(ull v) { return __int_as_float((int)(unsigned)(v >> 32)); }
__device__ __forceinline__ float sigm(float x) { return 1.0f / (1.0f + __expf(-x)); }

// release-add / acquire-load for the inter-CTA barrier (no full membars needed)
__device__ __forceinline__ void bar_signal(unsigned* p) {
    asm volatile("red.release.gpu.global.add.u32 [%0], 1;" :: "l"(p) : "memory");
}
__device__ __forceinline__ unsigned bar_peek(const unsigned* p) {
    unsigned v;
    asm volatile("ld.acquire.gpu.global.u32 %0, [%1];" : "=r"(v) : "l"(p) : "memory");
    return v;
}

// k-permutation: pos(k) interleaves the 16 k-slices so each slice's data is
// chunk-contiguous:  k = ks*32 + cc*4 + j  ->  pos = cc*64 + ks*4 + j
__device__ __forceinline__ int kpos(int k) {
    return (((k >> 2) & 7) << 6) + ((k >> 5) << 2) + (k & 3);
}

// ---------------- kernel 0: init (barrier reset + h0 permuted copy) ----------------
__global__ void init_kernel(const float* __restrict__ h0) {
    if (blockIdx.x == 0 && threadIdx.x < 8 * 32) g_bar[threadIdx.x] = 0u;
    int idx = blockIdx.x * blockDim.x + threadIdx.x;
    if (idx < BATCH * HDIM) {
        int b = idx >> 9;
        int k = idx & 511;
        g_h[0][b * HDIM + kpos(k)] = h0[idx];
    }
}

// ---------------- kernel 1: xg = x @ Wi + bi  (128x128x16 tile, 8x8/thread) ----------------
#define GBM 128
#define GBN 128
#define GBK 16
#define APITCH 132

__global__ __launch_bounds__(256) void xg_gemm(const float* __restrict__ X,
                                               const float* __restrict__ Wi,
                                               const float* __restrict__ bi) {
    __shared__ float At[GBK * APITCH];   // transposed A: At[k][m]
    __shared__ float Bs[GBK * GBN];      // Bs[k][n]

    const int tid = threadIdx.x;
    const int tx  = tid & 15;            // n-group
    const int ty  = tid >> 4;            // m-group
    const size_t m0 = (size_t)blockIdx.y * GBM;
    const int    n0 = blockIdx.x * GBN;

    const int arow = tid >> 2;           // 0..63
    const int ac4  = (tid & 3) << 2;     // 0,4,8,12
    const int brow = tid >> 5;           // 0..7
    const int bc4  = (tid & 31) << 2;    // 0..124

    const float* Xp = X + m0 * FDIM;
    const float* Wp = Wi + n0;

    ull acc[8][4];
    #pragma unroll
    for (int m = 0; m < 8; m++)
        #pragma unroll
        for (int n = 0; n < 4; n++) acc[m][n] = 0ull;

    float4 a0r = *(const float4*)(Xp + (size_t)arow        * FDIM + ac4);
    float4 a1r = *(const float4*)(Xp + (size_t)(arow + 64) * FDIM + ac4);
    float4 b0r = *(const float4*)(Wp + (size_t)brow       * G3 + bc4);
    float4 b1r = *(const float4*)(Wp + (size_t)(brow + 8) * G3 + bc4);

    for (int k0 = 0; k0 < FDIM; k0 += GBK) {
        At[(ac4 + 0) * APITCH + arow] = a0r.x;
        At[(ac4 + 1) * APITCH + arow] = a0r.y;
        At[(ac4 + 2) * APITCH + arow] = a0r.z;
        At[(ac4 + 3) * APITCH + arow] = a0r.w;
        At[(ac4 + 0) * APITCH + arow + 64] = a1r.x;
        At[(ac4 + 1) * APITCH + arow + 64] = a1r.y;
        At[(ac4 + 2) * APITCH + arow + 64] = a1r.z;
        At[(ac4 + 3) * APITCH + arow + 64] = a1r.w;
        *(float4*)&Bs[brow * GBN + bc4]       = b0r;
        *(float4*)&Bs[(brow + 8) * GBN + bc4] = b1r;
        __syncthreads();

        if (k0 + GBK < FDIM) {
            a0r = *(const float4*)(Xp + (size_t)arow        * FDIM + k0 + GBK + ac4);
            a1r = *(const float4*)(Xp + (size_t)(arow + 64) * FDIM + k0 + GBK + ac4);
            b0r = *(const float4*)(Wp + (size_t)(k0 + GBK + brow)     * G3 + bc4);
            b1r = *(const float4*)(Wp + (size_t)(k0 + GBK + brow + 8) * G3 + bc4);
        }

        #pragma unroll
        for (int k = 0; k < GBK; k++) {
            float4 av0 = *(const float4*)&At[k * APITCH + ty * 8];
            float4 av1 = *(const float4*)&At[k * APITCH + ty * 8 + 4];
            ulonglong2 bv0 = *(const ulonglong2*)&Bs[k * GBN + tx * 8];
            ulonglong2 bv1 = *(const ulonglong2*)&Bs[k * GBN + tx * 8 + 4];
            float am[8] = {av0.x, av0.y, av0.z, av0.w, av1.x, av1.y, av1.z, av1.w};
            #pragma unroll
            for (int m = 0; m < 8; m++) {
                ull d = dup2(am[m]);
                acc[m][0] = ffma2(d, bv0.x, acc[m][0]);
                acc[m][1] = ffma2(d, bv0.y, acc[m][1]);
                acc[m][2] = ffma2(d, bv1.x, acc[m][2]);
                acc[m][3] = ffma2(d, bv1.y, acc[m][3]);
            }
        }
        __syncthreads();
    }

    float4 bias0 = *(const float4*)(bi + n0 + tx * 8);
    float4 bias1 = *(const float4*)(bi + n0 + tx * 8 + 4);
    #pragma unroll
    for (int m = 0; m < 8; m++) {
        size_t row = m0 + (size_t)ty * 8 + m;
        float4 o0, o1;
        o0.x = lo32(acc[m][0]) + bias0.x;  o0.y = hi32(acc[m][0]) + bias0.y;
        o0.z = lo32(acc[m][1]) + bias0.z;  o0.w = hi32(acc[m][1]) + bias0.w;
        o1.x = lo32(acc[m][2]) + bias1.x;  o1.y = hi32(acc[m][2]) + bias1.y;
        o1.z = lo32(acc[m][3]) + bias1.z;  o1.w = hi32(acc[m][3]) + bias1.w;
        *(float4*)(g_xg + row * G3 + n0 + tx * 8)     = o0;
        *(float4*)(g_xg + row * G3 + n0 + tx * 8 + 4) = o1;
    }
}

// ---------------- kernel 2: persistent GRU scan (R8-good config + all-thread poll) ----------------
// 128 blocks = 8 batch-groups x 16 col-groups; barrier across the 16 CTAs of a
// batch-group. 256 threads = 16 register tiles (4 batches x 4 H-cols) x 16-way
// k-split. Lane map: warp = col-tile (w loads half-warp-broadcast), half-warp =
// batch-tile.
#define RBLOCKS   128
#define RTHREADS  256
#define WSZ       (96 * 512)
#define HSZ       (8 * 512)
#define RSTRIDE   197
#define RSZ       (16 * RSTRIDE)
#define SMEM_REC  ((WSZ + HSZ + RSZ) * 4)

__global__ __launch_bounds__(RTHREADS, 1) void gru_rec(const float* __restrict__ Wh,
                                                       const float* __restrict__ bhn,
                                                       float* __restrict__ ys) {
    extern __shared__ float smem[];
    float* w_s   = smem;               // 96 rows (c*3+g) x 512 (permuted k)
    float* h_s   = smem + WSZ;         // 8 rows (batch)  x 512 (permuted k)
    float* red_s = h_s + HSZ;          // 16 tiles x RSTRIDE (48 sums x 4 partials)

    const int tid  = threadIdx.x;
    const int lane = tid & 31;
    const int warp = tid >> 5;
    const int ct   = warp;               // col-tile 0..7  (per-warp: w broadcast)
    const int bt   = lane >> 4;          // batch-tile 0..1 (per-half)
    const int ks   = lane & 15;          // k-slice 0..15
    const int tile = bt * 8 + ct;

    const int bg = blockIdx.x >> 4;      // batch group 0..7
    const int cg = blockIdx.x & 15;      // col group 0..15
    unsigned* barp = &g_bar[bg * 32];

    // epilogue identity: thread -> one (batch, H-col) output
    const int lb    = tid >> 5;          // 0..7
    const int lc    = tid & 31;          // 0..31
    const int bglob = bg * 8 + lb;
    const int colg  = cg * 32 + lc;
    const int posc  = ((lc >> 2) << 6) + (cg << 2) + (lc & 3);  // kpos(colg)
    const float bh  = bhn[colg];

    // ---- stage Wh slice once (permuted k) ----
    for (int idx = tid; idx < 96 * 512; idx += RTHREADS) {
        int k = idx / 96;
        int m = idx - k * 96;
        int g = m >> 5, c = m & 31;
        float v = Wh[(size_t)k * G3 + g * HDIM + cg * 32 + c];
        w_s[(c * 3 + g) * 512 + kpos(k)] = v;
    }
    __syncthreads();

    const float* hb = h_s + (bt * 4) * 512 + ks * 4;
    const float* wb = w_s + ct * 12 * 512 + ks * 4;
    const float* xgq = g_xg + (size_t)bglob * G3 + colg;

    // prefetch xg for t=0
    float xr = __ldg(xgq);
    float xz = __ldg(xgq + HDIM);
    float xn = __ldg(xgq + 2 * HDIM);

    for (int t = 0; t < T_STEPS; t++) {
        // ---- stage h slice (16KB straight copy; src already permuted) ----
        const float4* hsrc = (const float4*)(g_h[t & 1] + (size_t)bg * 8 * HDIM);
        float4 v0 = __ldcg(hsrc + tid);
        float4 v1 = __ldcg(hsrc + 256 + tid);
        float4 v2 = __ldcg(hsrc + 512 + tid);
        float4 v3 = __ldcg(hsrc + 768 + tid);
        ((float4*)h_s)[tid]       = v0;
        ((float4*)h_s)[256 + tid] = v1;
        ((float4*)h_s)[512 + tid] = v2;
        ((float4*)h_s)[768 + tid] = v3;
        __syncthreads();

        // ---- register-tiled dots: 4 batches x 12 gate-cols x 32 k ----
        ull acc[4][12];
        #pragma unroll
        for (int b = 0; b < 4; b++)
            #pragma unroll
            for (int i = 0; i < 12; i++) acc[b][i] = 0ull;

        #pragma unroll 2
        for (int cc = 0; cc < 8; cc++) {
            const float* hc = hb + cc * 64;
            const float* wc = wb + cc * 64;
            ulonglong2 hv[4];
            #pragma unroll
            for (int b = 0; b < 4; b++) hv[b] = *(const ulonglong2*)(hc + b * 512);
            #pragma unroll
            for (int i = 0; i < 12; i++) {
                ulonglong2 wv = *(const ulonglong2*)(wc + i * 512);
                #pragma unroll
                for (int b = 0; b < 4; b++) {
                    acc[b][i] = ffma2(hv[b].x, wv.x, acc[b][i]);
                    acc[b][i] = ffma2(hv[b].y, wv.y, acc[b][i]);
                }
            }
        }

        // ---- fold f32x2 -> f32, 2 shuffle rounds (16 ks -> 4 partials) ----
        float s[48];
        #pragma unroll
        for (int b = 0; b < 4; b++)
            #pragma unroll
            for (int i = 0; i < 12; i++) {
                ull v = acc[b][i];
                s[b * 12 + i] = lo32(v) + hi32(v);
            }
        #pragma unroll
        for (int i = 0; i < 48; i++) s[i] += __shfl_xor_sync(0xffffffffu, s[i], 1);
        #pragma unroll
        for (int i = 0; i < 48; i++) s[i] += __shfl_xor_sync(0xffffffffu, s[i], 2);

        if ((ks & 3) == 0) {
            float* rp = red_s + tile * RSTRIDE + (ks >> 2);
            #pragma unroll
            for (int i = 0; i < 48; i++) rp[i * 4] = s[i];
        }
        __syncthreads();

        // ---- gather 4 partials x 3 gates, compute GRU update ----
        const float* rp = red_s + ((lb >> 2) * 8 + (lc >> 2)) * RSTRIDE
                        + (lb & 3) * 48 + (lc & 3) * 12;
        float hr = rp[0] + rp[1] + rp[2]  + rp[3];
        float hz = rp[4] + rp[5] + rp[6]  + rp[7];
        float hn = rp[8] + rp[9] + rp[10] + rp[11];
        float hold = h_s[lb * 512 + posc];
        float r = sigm(xr + hr);
        float z = sigm(xz + hz);
        float n = tanhf(xn + r * (hn + bh));
        float hnew = (1.0f - z) * n + z * hold;

        // h store precedes the release; all other work hides in the poll window
        __stcg(&g_h[(t + 1) & 1][bglob * HDIM + posc], hnew);
        __syncthreads();                      // all stcg in this CTA done
        if (tid == 0) bar_signal(barp);

        // poll-window work: ys store + next xg prefetch
        ys[((size_t)t * BATCH + bglob) * HDIM + colg] = hnew;
        float nxr = 0.f, nxz = 0.f, nxn = 0.f;
        if (t + 1 < T_STEPS) {
            const float* xb = xgq + (size_t)(t + 1) * (BATCH * G3);
            nxr = __ldg(xb);
            nxz = __ldg(xb + HDIM);
            nxn = __ldg(xb + 2 * HDIM);
        }

        // all threads poll (uniform addr = 1 req/warp); own acquire orders the
        // next iteration's __ldcg reads — no trailing __syncthreads needed.
        {
            unsigned target = 16u * (unsigned)(t + 1);
            while (bar_peek(barp) < target) { }
        }
        xr = nxr; xz = nxz; xn = nxn;
    }
}

// ---------------- launcher ----------------
extern "C" void kernel_launch(void* const* d_in, const int* in_sizes, int n_in,
                              void* d_out, int out_size) {
    (void)in_sizes; (void)n_in; (void)out_size;
    const float* x   = (const float*)d_in[0];
    const float* h0  = (const float*)d_in[1];
    const float* Wi  = (const float*)d_in[2];
    const float* bi  = (const float*)d_in[3];
    const float* Wh  = (const float*)d_in[4];
    const float* bhn = (const float*)d_in[5];
    float* ys = (float*)d_out;

    cudaFuncSetAttribute(gru_rec, cudaFuncAttributeMaxDynamicSharedMemorySize, SMEM_REC);

    init_kernel<<<64, 512>>>(h0);

    dim3 ggrid(G3 / GBN, (T_STEPS * BATCH) / GBM);   // 12 x 512
    xg_gemm<<<ggrid, 256>>>(x, Wi, bi);

    gru_rec<<<RBLOCKS, RTHREADS, SMEM_REC>>>(Wh, bhn, ys);
}

// round 13
// speedup vs baseline: 1.5254x; 1.5254x over previous
#include <cuda_runtime.h>
#include <cstdint>
#include <cstddef>

#define T_STEPS 1024
#define BATCH   64
#define FDIM    256
#define HDIM    512
#define G3      (3*HDIM)   /* 1536 */

typedef unsigned long long ull;

// ---------------- static scratch (allocation-free per harness rules) ----------------
__device__ float    g_xg[(size_t)T_STEPS * BATCH * G3];   // input projections
__device__ float    g_h[2][BATCH * HDIM];                 // ping-pong hidden state [b][pos(k)]
__device__ unsigned g_bar[8 * 32];                        // per-batch-group barrier (padded lines)

// ---------------- helpers ----------------
__device__ __forceinline__ ull ffma2(ull a, ull b, ull c) {
    ull d;
    asm("fma.rn.f32x2 %0, %1, %2, %3;" : "=l"(d) : "l"(a), "l"(b), "l"(c));
    return d;
}
__device__ __forceinline__ ull dup2(float a) {
    ull d;
    asm("mov.b64 %0, {%1, %1};" : "=l"(d) : "f"(a));
    return d;
}
__device__ __forceinline__ float lo32(ull v) { return __int_as_float((int)(unsigned)(v & 0xffffffffull)); }
__device__ __forceinline__ float hi32(ull v) { return __int_as_float((int)(unsigned)(v >> 32)); }
__device__ __forceinline__ float sigm(float x) { return 1.0f / (1.0f + __expf(-x)); }

// release-add / acquire-load for the inter-CTA barrier (no full membars needed)
__device__ __forceinline__ void bar_signal(unsigned* p) {
    asm volatile("red.release.gpu.global.add.u32 [%0], 1;" :: "l"(p) : "memory");
}
__device__ __forceinline__ unsigned bar_peek(const unsigned* p) {
    unsigned v;
    asm volatile("ld.acquire.gpu.global.u32 %0, [%1];" : "=r"(v) : "l"(p) : "memory");
    return v;
}

// L2-direct async copy (LDGSTS.BYPASS): bypasses the non-coherent L1 like __ldcg,
// but lands directly in smem with no register round-trip.
__device__ __forceinline__ void cp_async16(unsigned dst, const void* src) {
    asm volatile("cp.async.cg.shared.global [%0], [%1], 16;" :: "r"(dst), "l"(src));
}
__device__ __forceinline__ void cp_commit() { asm volatile("cp.async.commit_group;"); }
__device__ __forceinline__ void cp_wait0()  { asm volatile("cp.async.wait_group 0;" ::: "memory"); }

// k-permutation: pos(k) interleaves the 16 k-slices so each slice's data is
// chunk-contiguous:  k = ks*32 + cc*4 + j  ->  pos = cc*64 + ks*4 + j
__device__ __forceinline__ int kpos(int k) {
    return (((k >> 2) & 7) << 6) + ((k >> 5) << 2) + (k & 3);
}

// ---------------- kernel 0: init (barrier reset + h0 permuted copy) ----------------
__global__ void init_kernel(const float* __restrict__ h0) {
    if (blockIdx.x == 0 && threadIdx.x < 8 * 32) g_bar[threadIdx.x] = 0u;
    int idx = blockIdx.x * blockDim.x + threadIdx.x;
    if (idx < BATCH * HDIM) {
        int b = idx >> 9;
        int k = idx & 511;
        g_h[0][b * HDIM + kpos(k)] = h0[idx];
    }
}

// ---------------- kernel 1: xg = x @ Wi + bi  (128x128x16 tile, 8x8/thread) ----------------
#define GBM 128
#define GBN 128
#define GBK 16
#define APITCH 132

__global__ __launch_bounds__(256) void xg_gemm(const float* __restrict__ X,
                                               const float* __restrict__ Wi,
                                               const float* __restrict__ bi) {
    __shared__ float At[GBK * APITCH];   // transposed A: At[k][m]
    __shared__ float Bs[GBK * GBN];      // Bs[k][n]

    const int tid = threadIdx.x;
    const int tx  = tid & 15;            // n-group
    const int ty  = tid >> 4;            // m-group
    const size_t m0 = (size_t)blockIdx.y * GBM;
    const int    n0 = blockIdx.x * GBN;

    const int arow = tid >> 2;           // 0..63
    const int ac4  = (tid & 3) << 2;     // 0,4,8,12
    const int brow = tid >> 5;           // 0..7
    const int bc4  = (tid & 31) << 2;    // 0..124

    const float* Xp = X + m0 * FDIM;
    const float* Wp = Wi + n0;

    ull acc[8][4];
    #pragma unroll
    for (int m = 0; m < 8; m++)
        #pragma unroll
        for (int n = 0; n < 4; n++) acc[m][n] = 0ull;

    float4 a0r = *(const float4*)(Xp + (size_t)arow        * FDIM + ac4);
    float4 a1r = *(const float4*)(Xp + (size_t)(arow + 64) * FDIM + ac4);
    float4 b0r = *(const float4*)(Wp + (size_t)brow       * G3 + bc4);
    float4 b1r = *(const float4*)(Wp + (size_t)(brow + 8) * G3 + bc4);

    for (int k0 = 0; k0 < FDIM; k0 += GBK) {
        At[(ac4 + 0) * APITCH + arow] = a0r.x;
        At[(ac4 + 1) * APITCH + arow] = a0r.y;
        At[(ac4 + 2) * APITCH + arow] = a0r.z;
        At[(ac4 + 3) * APITCH + arow] = a0r.w;
        At[(ac4 + 0) * APITCH + arow + 64] = a1r.x;
        At[(ac4 + 1) * APITCH + arow + 64] = a1r.y;
        At[(ac4 + 2) * APITCH + arow + 64] = a1r.z;
        At[(ac4 + 3) * APITCH + arow + 64] = a1r.w;
        *(float4*)&Bs[brow * GBN + bc4]       = b0r;
        *(float4*)&Bs[(brow + 8) * GBN + bc4] = b1r;
        __syncthreads();

        if (k0 + GBK < FDIM) {
            a0r = *(const float4*)(Xp + (size_t)arow        * FDIM + k0 + GBK + ac4);
            a1r = *(const float4*)(Xp + (size_t)(arow + 64) * FDIM + k0 + GBK + ac4);
            b0r = *(const float4*)(Wp + (size_t)(k0 + GBK + brow)     * G3 + bc4);
            b1r = *(const float4*)(Wp + (size_t)(k0 + GBK + brow + 8) * G3 + bc4);
        }

        #pragma unroll
        for (int k = 0; k < GBK; k++) {
            float4 av0 = *(const float4*)&At[k * APITCH + ty * 8];
            float4 av1 = *(const float4*)&At[k * APITCH + ty * 8 + 4];
            ulonglong2 bv0 = *(const ulonglong2*)&Bs[k * GBN + tx * 8];
            ulonglong2 bv1 = *(const ulonglong2*)&Bs[k * GBN + tx * 8 + 4];
            float am[8] = {av0.x, av0.y, av0.z, av0.w, av1.x, av1.y, av1.z, av1.w};
            #pragma unroll
            for (int m = 0; m < 8; m++) {
                ull d = dup2(am[m]);
                acc[m][0] = ffma2(d, bv0.x, acc[m][0]);
                acc[m][1] = ffma2(d, bv0.y, acc[m][1]);
                acc[m][2] = ffma2(d, bv1.x, acc[m][2]);
                acc[m][3] = ffma2(d, bv1.y, acc[m][3]);
            }
        }
        __syncthreads();
    }

    float4 bias0 = *(const float4*)(bi + n0 + tx * 8);
    float4 bias1 = *(const float4*)(bi + n0 + tx * 8 + 4);
    #pragma unroll
    for (int m = 0; m < 8; m++) {
        size_t row = m0 + (size_t)ty * 8 + m;
        float4 o0, o1;
        o0.x = lo32(acc[m][0]) + bias0.x;  o0.y = hi32(acc[m][0]) + bias0.y;
        o0.z = lo32(acc[m][1]) + bias0.z;  o0.w = hi32(acc[m][1]) + bias0.w;
        o1.x = lo32(acc[m][2]) + bias1.x;  o1.y = hi32(acc[m][2]) + bias1.y;
        o1.z = lo32(acc[m][3]) + bias1.z;  o1.w = hi32(acc[m][3]) + bias1.w;
        *(float4*)(g_xg + row * G3 + n0 + tx * 8)     = o0;
        *(float4*)(g_xg + row * G3 + n0 + tx * 8 + 4) = o1;
    }
}

// ---------------- kernel 2: persistent GRU scan (R8-good config, verbatim,
// + cp.async h staging + early xg prefetch) ----------------
// 128 blocks = 8 batch-groups x 16 col-groups; barrier across the 16 CTAs of a
// batch-group. 256 threads = 16 register tiles (4 batches x 4 H-cols) x 16-way
// k-split. Lane map: warp = col-tile (w loads half-warp-broadcast), half-warp =
// batch-tile.
#define RBLOCKS   128
#define RTHREADS  256
#define WSZ       (96 * 512)
#define HSZ       (8 * 512)
#define RSTRIDE   197
#define RSZ       (16 * RSTRIDE)
#define SMEM_REC  ((WSZ + HSZ + RSZ) * 4)

__global__ __launch_bounds__(RTHREADS, 1) void gru_rec(const float* __restrict__ Wh,
                                                       const float* __restrict__ bhn,
                                                       float* __restrict__ ys) {
    extern __shared__ float smem[];
    float* w_s   = smem;               // 96 rows (c*3+g) x 512 (permuted k)
    float* h_s   = smem + WSZ;         // 8 rows (batch)  x 512 (permuted k)
    float* red_s = h_s + HSZ;          // 16 tiles x RSTRIDE (48 sums x 4 partials)

    const int tid  = threadIdx.x;
    const int lane = tid & 31;
    const int warp = tid >> 5;
    const int ct   = warp;               // col-tile 0..7  (per-warp: w broadcast)
    const int bt   = lane >> 4;          // batch-tile 0..1 (per-half)
    const int ks   = lane & 15;          // k-slice 0..15
    const int tile = bt * 8 + ct;

    const int bg = blockIdx.x >> 4;      // batch group 0..7
    const int cg = blockIdx.x & 15;      // col group 0..15
    unsigned* barp = &g_bar[bg * 32];

    // epilogue identity: thread -> one (batch, H-col) output
    const int lb    = tid >> 5;          // 0..7
    const int lc    = tid & 31;          // 0..31
    const int bglob = bg * 8 + lb;
    const int colg  = cg * 32 + lc;
    const int posc  = ((lc >> 2) << 6) + (cg << 2) + (lc & 3);  // kpos(colg)
    const float bh  = bhn[colg];

    // ---- stage Wh slice once (permuted k) ----
    for (int idx = tid; idx < 96 * 512; idx += RTHREADS) {
        int k = idx / 96;
        int m = idx - k * 96;
        int g = m >> 5, c = m & 31;
        float v = Wh[(size_t)k * G3 + g * HDIM + cg * 32 + c];
        w_s[(c * 3 + g) * 512 + kpos(k)] = v;
    }
    __syncthreads();

    const float* hb = h_s + (bt * 4) * 512 + ks * 4;
    const float* wb = w_s + ct * 12 * 512 + ks * 4;
    const float* xgq = g_xg + (size_t)bglob * G3 + colg;
    const unsigned hs_u32 = (unsigned)__cvta_generic_to_shared(h_s);

    // prefetch xg for t=0
    float xr = __ldg(xgq);
    float xz = __ldg(xgq + HDIM);
    float xn = __ldg(xgq + 2 * HDIM);

    for (int t = 0; t < T_STEPS; t++) {
        // ---- stage h slice: 16KB straight copy via cp.async.cg (L2-direct,
        // no register round-trip; src already permuted) ----
        const float4* hsrc = (const float4*)(g_h[t & 1] + (size_t)bg * 8 * HDIM);
        cp_async16(hs_u32 + tid * 16,         hsrc + tid);
        cp_async16(hs_u32 + 4096 + tid * 16,  hsrc + 256 + tid);
        cp_async16(hs_u32 + 8192 + tid * 16,  hsrc + 512 + tid);
        cp_async16(hs_u32 + 12288 + tid * 16, hsrc + 768 + tid);
        cp_commit();

        // early prefetch of NEXT step's xg (independent of the barrier): the
        // whole dot phase (~4000 cyc) hides the DRAM latency.
        float nxr = 0.f, nxz = 0.f, nxn = 0.f;
        if (t + 1 < T_STEPS) {
            const float* xb = xgq + (size_t)(t + 1) * (BATCH * G3);
            nxr = __ldg(xb);
            nxz = __ldg(xb + HDIM);
            nxn = __ldg(xb + 2 * HDIM);
        }

        cp_wait0();
        __syncthreads();

        // ---- register-tiled dots: 4 batches x 12 gate-cols x 32 k ----
        ull acc[4][12];
        #pragma unroll
        for (int b = 0; b < 4; b++)
            #pragma unroll
            for (int i = 0; i < 12; i++) acc[b][i] = 0ull;

        #pragma unroll 2
        for (int cc = 0; cc < 8; cc++) {
            const float* hc = hb + cc * 64;
            const float* wc = wb + cc * 64;
            ulonglong2 hv[4];
            #pragma unroll
            for (int b = 0; b < 4; b++) hv[b] = *(const ulonglong2*)(hc + b * 512);
            #pragma unroll
            for (int i = 0; i < 12; i++) {
                ulonglong2 wv = *(const ulonglong2*)(wc + i * 512);
                #pragma unroll
                for (int b = 0; b < 4; b++) {
                    acc[b][i] = ffma2(hv[b].x, wv.x, acc[b][i]);
                    acc[b][i] = ffma2(hv[b].y, wv.y, acc[b][i]);
                }
            }
        }

        // ---- fold f32x2 -> f32, 2 shuffle rounds (16 ks -> 4 partials) ----
        float s[48];
        #pragma unroll
        for (int b = 0; b < 4; b++)
            #pragma unroll
            for (int i = 0; i < 12; i++) {
                ull v = acc[b][i];
                s[b * 12 + i] = lo32(v) + hi32(v);
            }
        #pragma unroll
        for (int i = 0; i < 48; i++) s[i] += __shfl_xor_sync(0xffffffffu, s[i], 1);
        #pragma unroll
        for (int i = 0; i < 48; i++) s[i] += __shfl_xor_sync(0xffffffffu, s[i], 2);

        if ((ks & 3) == 0) {
            float* rp = red_s + tile * RSTRIDE + (ks >> 2);
            #pragma unroll
            for (int i = 0; i < 48; i++) rp[i * 4] = s[i];
        }
        __syncthreads();

        // ---- gather 4 partials x 3 gates, compute GRU update ----
        const float* rp = red_s + ((lb >> 2) * 8 + (lc >> 2)) * RSTRIDE
                        + (lb & 3) * 48 + (lc & 3) * 12;
        float hr = rp[0] + rp[1] + rp[2]  + rp[3];
        float hz = rp[4] + rp[5] + rp[6]  + rp[7];
        float hn = rp[8] + rp[9] + rp[10] + rp[11];
        float hold = h_s[lb * 512 + posc];
        float r = sigm(xr + hr);
        float z = sigm(xz + hz);
        float n = tanhf(xn + r * (hn + bh));
        float hnew = (1.0f - z) * n + z * hold;

        // h store precedes the release; ys store hides in the poll window
        __stcg(&g_h[(t + 1) & 1][bglob * HDIM + posc], hnew);
        __syncthreads();                      // all stcg in this CTA done
        if (tid == 0) bar_signal(barp);

        ys[((size_t)t * BATCH + bglob) * HDIM + colg] = hnew;

        if (tid == 0) {
            unsigned target = 16u * (unsigned)(t + 1);
            while (bar_peek(barp) < target) { }
        }
        __syncthreads();
        xr = nxr; xz = nxz; xn = nxn;
    }
}

// ---------------- launcher ----------------
extern "C" void kernel_launch(void* const* d_in, const int* in_sizes, int n_in,
                              void* d_out, int out_size) {
    (void)in_sizes; (void)n_in; (void)out_size;
    const float* x   = (const float*)d_in[0];
    const float* h0  = (const float*)d_in[1];
    const float* Wi  = (const float*)d_in[2];
    const float* bi  = (const float*)d_in[3];
    const float* Wh  = (const float*)d_in[4];
    const float* bhn = (const float*)d_in[5];
    float* ys = (float*)d_out;

    cudaFuncSetAttribute(gru_rec, cudaFuncAttributeMaxDynamicSharedMemorySize, SMEM_REC);

    init_kernel<<<64, 512>>>(h0);

    dim3 ggrid(G3 / GBN, (T_STEPS * BATCH) / GBM);   // 12 x 512
    xg_gemm<<<ggrid, 256>>>(x, Wi, bi);

    gru_rec<<<RBLOCKS, RTHREADS, SMEM_REC>>>(Wh, bhn, ys);
}